// round 1
// baseline (speedup 1.0000x reference)
#include <cuda_runtime.h>

#define N_NODES 100000
#define N_EDGES 50000
#define NNZ     3200000
#define D       32
#define ALPHA   0.5f

// ---------------- device scratch (no allocs allowed) ----------------
__device__ __align__(256) float g_X1[N_NODES * D];   // X @ W1 + b1
__device__ __align__(256) float g_G [N_NODES * D];   // sum of Xe[edges[i]] into vertex[i]
__device__ float g_deg[N_NODES];                     // incidence count per vertex
__device__ int   g_start[N_EDGES + 1];               // CSR bounds of sorted `edges`
__device__ float g_M1[D * D];                        // W2a @ W_w
__device__ float g_M2[D * D];                        // W2b @ W_w
__device__ float g_c1[D];                            // W2_b @ W_w

// ---------------- init: zero scratch + fold small matrices ----------------
__global__ void k_init(const float* __restrict__ W2w,
                       const float* __restrict__ W2b,
                       const float* __restrict__ Ww) {
    int tid = blockIdx.x * blockDim.x + threadIdx.x;
    int stride = gridDim.x * blockDim.x;
    const int total = N_NODES * D + N_NODES + (N_EDGES + 1);
    for (int i = tid; i < total; i += stride) {
        if (i < N_NODES * D)                  g_G[i] = 0.f;
        else if (i < N_NODES * D + N_NODES)   g_deg[i - N_NODES * D] = 0.f;
        else                                  g_start[i - N_NODES * D - N_NODES] = NNZ;
    }
    if (tid < D * D) {
        int k = tid >> 5, j = tid & 31;
        float s1 = 0.f, s2 = 0.f;
        #pragma unroll
        for (int m = 0; m < D; m++) {
            s1 = fmaf(W2w[k * D + m],        Ww[m * D + j], s1);
            s2 = fmaf(W2w[(D + k) * D + m],  Ww[m * D + j], s2);
        }
        g_M1[tid] = s1;
        g_M2[tid] = s2;
        if (k == 0) {
            float c = 0.f;
            #pragma unroll
            for (int m = 0; m < D; m++) c = fmaf(W2b[m], Ww[m * D + j], c);
            g_c1[j] = c;
        }
    }
}

// ---------------- segment bounds: g_start[e] = lower_bound(edges, e) ----------------
__global__ void k_fill(const int* __restrict__ edges) {
    int tid = blockIdx.x * blockDim.x + threadIdx.x;
    int stride = gridDim.x * blockDim.x;
    for (int i = tid; i < NNZ; i += stride) {
        int e = edges[i];
        int p = (i == 0) ? -1 : edges[i - 1];
        if (e != p)
            for (int k = p + 1; k <= e; k++) g_start[k] = i;
    }
}

// ---------------- vertex degrees ----------------
__global__ void k_deg(const int* __restrict__ vertex) {
    int tid = blockIdx.x * blockDim.x + threadIdx.x;
    int stride = gridDim.x * blockDim.x;
    for (int i = tid; i < NNZ; i += stride)
        atomicAdd(&g_deg[vertex[i]], 1.0f);
}

// ---------------- X1 = X @ W1 + b1 (warp per node, lane = out column) ----------------
__global__ void k_x1(const float* __restrict__ X,
                     const float* __restrict__ W1w,
                     const float* __restrict__ W1b) {
    __shared__ float sW[D * D];
    __shared__ float sb[D];
    int t = threadIdx.x;
    for (int i = t; i < D * D; i += blockDim.x) sW[i] = W1w[i];
    if (t < D) sb[t] = W1b[t];
    __syncthreads();

    int lane = t & 31;
    int warp = (blockIdx.x * blockDim.x + t) >> 5;
    int nwarps = (gridDim.x * blockDim.x) >> 5;
    for (int v = warp; v < N_NODES; v += nwarps) {
        float x = X[v * D + lane];
        float acc = sb[lane];
        #pragma unroll
        for (int k = 0; k < D; k++)
            acc = fmaf(__shfl_sync(0xffffffffu, x, k), sW[k * D + lane], acc);
        g_X1[v * D + lane] = acc;
    }
}

// ---------------- fused: Xe[e] = sum(atts*X1[vertex]) over sorted segment,
//                  then scatter Xe[e] into G[vertex[i]] with vector reds ------------
__global__ void k_edge(const int* __restrict__ vertex,
                       const float* __restrict__ atts) {
    int t = threadIdx.x;
    int lane = t & 31;
    int warp = (blockIdx.x * blockDim.x + t) >> 5;
    int nwarps = (gridDim.x * blockDim.x) >> 5;

    for (int e = warp; e < N_EDGES; e += nwarps) {
        int s = g_start[e];
        int tEnd = g_start[e + 1];
        if (s >= tEnd) continue;

        // segmented reduction: lane = column, serial over incidences (sorted run)
        float acc = 0.f;
        #pragma unroll 4
        for (int i = s; i < tEnd; i++) {
            int v = __ldg(&vertex[i]);           // uniform across warp -> 1 transaction
            float a = __ldg(&atts[i]);
            acc = fmaf(a, g_X1[v * D + lane], acc);  // coalesced 128B, L2-resident
        }

        // transpose row (1 float/lane) -> float4/lane so each red covers 16B;
        // 4 incidence rows scattered per warp red instruction
        int grp = lane & 7;                      // column group (4 floats)
        int sub = lane >> 3;                     // which of 4 rows this lane serves
        float4 val;
        val.x = __shfl_sync(0xffffffffu, acc, grp * 4 + 0);
        val.y = __shfl_sync(0xffffffffu, acc, grp * 4 + 1);
        val.z = __shfl_sync(0xffffffffu, acc, grp * 4 + 2);
        val.w = __shfl_sync(0xffffffffu, acc, grp * 4 + 3);

        for (int base = s; base < tEnd; base += 4) {
            int i = base + sub;
            if (i < tEnd) {
                int v = vertex[i];
                float* p = &g_G[v * D + grp * 4];
                asm volatile("red.global.add.v4.f32 [%0], {%1, %2, %3, %4};"
                             :: "l"(p), "f"(val.x), "f"(val.y), "f"(val.z), "f"(val.w)
                             : "memory");
            }
        }
    }
}

// ---------------- out = (1-a)*deg*(X@M1 + c1) + (1-a)*G@M2 + a*X0@W + Wb ----------
__global__ void k_out(const float* __restrict__ X,
                      const float* __restrict__ X0,
                      const float* __restrict__ Ww,
                      const float* __restrict__ Wb,
                      float* __restrict__ out) {
    __shared__ float sM1[D * D], sM2[D * D], sM3[D * D];
    __shared__ float sc1[D], sWb[D];
    int t = threadIdx.x;
    for (int i = t; i < D * D; i += blockDim.x) {
        sM1[i] = g_M1[i];
        sM2[i] = g_M2[i];
        sM3[i] = Ww[i];
    }
    if (t < D) { sc1[t] = g_c1[t]; sWb[t] = Wb[t]; }
    __syncthreads();

    int lane = t & 31;
    int warp = (blockIdx.x * blockDim.x + t) >> 5;
    int nwarps = (gridDim.x * blockDim.x) >> 5;
    for (int v = warp; v < N_NODES; v += nwarps) {
        float x  = X [v * D + lane];
        float g  = g_G[v * D + lane];
        float x0 = X0[v * D + lane];
        float d  = g_deg[v];
        float a1 = 0.f, a2 = 0.f, a3 = 0.f;
        #pragma unroll
        for (int k = 0; k < D; k++) {
            a1 = fmaf(__shfl_sync(0xffffffffu, x,  k), sM1[k * D + lane], a1);
            a2 = fmaf(__shfl_sync(0xffffffffu, g,  k), sM2[k * D + lane], a2);
            a3 = fmaf(__shfl_sync(0xffffffffu, x0, k), sM3[k * D + lane], a3);
        }
        out[v * D + lane] = (1.f - ALPHA) * (d * (a1 + sc1[lane]) + a2)
                          + ALPHA * a3 + sWb[lane];
    }
}

// ---------------- launch ----------------
extern "C" void kernel_launch(void* const* d_in, const int* in_sizes, int n_in,
                              void* d_out, int out_size) {
    const float* X    = (const float*)d_in[0];
    const float* X0   = (const float*)d_in[1];
    const float* atts = (const float*)d_in[2];
    const float* W1w  = (const float*)d_in[3];
    const float* W1b  = (const float*)d_in[4];
    const float* W2w  = (const float*)d_in[5];
    const float* W2b  = (const float*)d_in[6];
    const float* Ww   = (const float*)d_in[7];
    const float* Wb   = (const float*)d_in[8];
    const int* vertex = (const int*)d_in[9];
    const int* edges  = (const int*)d_in[10];
    float* out = (float*)d_out;

    k_init<<<2048, 256>>>(W2w, W2b, Ww);
    k_fill<<<2048, 256>>>(edges);
    k_deg <<<2048, 256>>>(vertex);
    k_x1  <<<1184, 256>>>(X, W1w, W1b);
    k_edge<<<6250, 256>>>(vertex, atts);   // exactly 50k warps = 1 warp / hyperedge
    k_out <<<1184, 256>>>(X, X0, Ww, Wb, out);
}